// round 14
// baseline (speedup 1.0000x reference)
#include <cuda_runtime.h>
#include <math.h>

#define BB 256
#define QQ 300
#define GG 16
#define KMAX 10     // ceil(QQ/32) columns per lane (LAP warp)
#define HQ 150      // q's per cost block
#define NTHR 160    // 5 warps per block
#define SCR_W 25

// ---------------- device scratch (no allocations allowed) ----------------
__device__ float              Cm_g[BB * GG * QQ];     // cost matrices, 4.9 MB
__device__ unsigned long long g_part[BB * 2 * GG];    // packed (key<<32|j) partial argmins
__device__ int                g_bdone[BB];            // per-batch half-counter (self-reset)
__device__ double             g_l1[BB];
__device__ double             g_bce[BB];
__device__ int                g_cnt[BB];
__device__ unsigned           g_done = 0;             // combine counter (self-reset)

__constant__ float c_tw[32] = {
    1.17236407f, 1.0166286f, 1.19620973f, 0.5544405f, 0.63531401f, 0.51258428f,
    1.08866652f, 1.15795989f, 1.07389395f, 0.98728399f, 1.12754142f, 1.05953744f,
    1.16945323f, 1.15512349f, 1.02097204f, 1.15795989f, 1.07147279f, 0.50627649f,
    1.07147279f, 0.61697221f, 1.16367678f, 1.0231585f, 1.18416106f, 1.04329092f,
    1.10645159f, 1.18416106f, 1.15795989f, 1.16367678f, 0.73949534f, 0.78760821f,
    1.08617476f, 1.00805777f
};

// order-preserving float <-> u32 key (finite + inf safe)
__device__ __forceinline__ unsigned f2key(float f) {
    unsigned u = __float_as_uint(f);
    return (u & 0x80000000u) ? ~u : (u | 0x80000000u);
}
__device__ __forceinline__ float key2f(unsigned k) {
    unsigned u = (k & 0x80000000u) ? (k & 0x7fffffffu) : ~k;
    return __uint_as_float(u);
}

// warp argmin (value, lowest index among minima)
__device__ __forceinline__ void warp_argmin(float val, int idx, float& mval, int& midx) {
    const unsigned mykey = f2key(val);
    const unsigned mkey  = __reduce_min_sync(0xffffffffu, mykey);
    const unsigned cand  = (mykey == mkey) ? (unsigned)idx : 0xffffffffu;
    midx = (int)__reduce_min_sync(0xffffffffu, cand);
    mval = key2f(mkey);
}

// ---- fused kernel: 2 cost blocks per batch; second finisher runs the LAP ----
__global__ __launch_bounds__(NTHR) void fused_kernel(
    const float* __restrict__ ph,
    const float* __restrict__ pr,
    const float* __restrict__ pt,
    const float* __restrict__ IVT,
    const int* __restrict__ iid,
    const int* __restrict__ vid,
    const int* __restrict__ tgt,
    const int* __restrict__ triplet,
    const int* __restrict__ mask,
    float* __restrict__ out)
{
    const int bid  = blockIdx.x;
    const int b    = bid >> 1;
    const int half = bid & 1;
    const int tid  = threadIdx.x;
    const int wrp  = tid >> 5;
    const int lane = tid & 31;

    __shared__ float scr[HQ * SCR_W];          // per-q logits (0..8 h, 9..21 r, 22..23 t)
    __shared__ unsigned long long s_part[GG][5];
    __shared__ float s_u[GG + 1];
    __shared__ int   s_p[QQ + 1];
    __shared__ int   s_way[QQ + 1];
    __shared__ int   si[GG], sv[GG], st[GG];
    __shared__ int   s_unass[GG];
    __shared__ float s_rmin[GG];
    __shared__ int   s_jm[GG];
    __shared__ int   s_old;

    if (tid < GG) {
        si[tid] = iid[b * GG + tid];
        sv[tid] = vid[b * GG + tid];
        st[tid] = tgt[b * GG + tid];
    }
    for (int j = tid; j <= QQ; j += NTHR) { s_p[j] = 0; s_way[j] = 0; }
    if (tid <= GG) s_u[tid] = 0.f;
    __syncthreads();

    // ---- cost phase: this block handles q in [half*HQ, half*HQ+HQ) ----
    float cv[GG];
#pragma unroll
    for (int g = 0; g < GG; g++) cv[g] = INFINITY;
    int jglob = QQ + 2;

    if (tid < HQ) {
        const int q = half * HQ + tid;
        jglob = q + 1;
        float* s = scr + tid * SCR_W;
        const float* hp = ph + (size_t)(b * QQ + q) * 9;
        const float* rp = pr + (size_t)(b * QQ + q) * 13;
        const float* tp = pt + (size_t)(b * QQ + q) * 2;

        float sh = 0.f, sr = 0.f, stt = 0.f;
#pragma unroll
        for (int i = 0; i < 9; i++)  { float x = hp[i]; s[i]      = x; sh  += __expf(x); }
#pragma unroll
        for (int i = 0; i < 13; i++) { float x = rp[i]; s[9 + i]  = x; sr  += __expf(x); }
#pragma unroll
        for (int i = 0; i < 2; i++)  { float x = tp[i]; s[22 + i] = x; stt += __expf(x); }

        const float lsum = __logf(sh) + __logf(sr) + __logf(stt);

        float* Cb = Cm_g + (size_t)b * GG * QQ;
#pragma unroll
        for (int g = 0; g < GG; g++) {
            float c = lsum - (s[si[g]] + s[9 + sv[g]] + s[22 + st[g]]);
            cv[g] = c;
            Cb[g * QQ + q] = c;
        }
    }

    // ---- per-g block argmin over this half's columns (packed key|j) ----
#pragma unroll
    for (int g = 0; g < GG; g++) {
        float mv; int mj;
        warp_argmin(cv[g], jglob, mv, mj);
        if (lane == 0)
            s_part[g][wrp] = ((unsigned long long)f2key(mv) << 32) | (unsigned)mj;
    }
    __syncthreads();
    if (tid < GG) {
        unsigned long long m = s_part[tid][0];
#pragma unroll
        for (int w = 1; w < 5; w++) m = min(m, s_part[tid][w]);
        g_part[(b * 2 + half) * GG + tid] = m;
    }

    // ---- handoff: second finisher for this batch runs the LAP ----
    __threadfence();
    __syncthreads();
    if (tid == 0) s_old = atomicAdd(&g_bdone[b], 1);
    __syncthreads();
    if (s_old == 0) return;                 // first half done; LAP belongs to the other block
    if (tid == 0) g_bdone[b] = 0;           // reset for next graph replay

    // ---- LAP (warp 0 only) ----
    if (tid >= 32) return;

    // BCE for this batch row
    double bce_row;
    {
        float x = IVT[b * 32 + lane];
        float t = (float)triplet[b * 32 + lane];
        float v = fmaxf(x, 0.f) - x * t + log1pf(__expf(-fabsf(x)));
        bce_row = (double)(c_tw[lane] * v);
#pragma unroll
        for (int off = 16; off > 0; off >>= 1)
            bce_row += __shfl_down_sync(0xffffffffu, bce_row, off);
    }

    // merge the two halves' row argmins
    if (lane < GG) {
        unsigned long long a = __ldcg(&g_part[(b * 2 + 0) * GG + lane]);
        unsigned long long c = __ldcg(&g_part[(b * 2 + 1) * GG + lane]);
        unsigned long long m = min(a, c);
        s_rmin[lane] = key2f((unsigned)(m >> 32));
        s_jm[lane]   = (int)(m & 0xffffffffu);
    }
    __syncwarp();

    unsigned mb = __ballot_sync(0xffffffffu, lane < GG && mask[b * GG + lane] != 0);
    const int n = __popc(mb);
    const float* Cb = Cm_g + (size_t)b * GG * QQ;

    float v[KMAX], minv[KMAX];
#pragma unroll
    for (int k = 0; k < KMAX; k++) v[k] = 0.f;

    // greedy init from merged row minima
    int n_unass = 0;
    if (lane == 0) {
        for (int i = 1; i <= n; i++) {
            s_u[i] = s_rmin[i - 1];
            int jm = s_jm[i - 1];
            if (s_p[jm] == 0) s_p[jm] = i;
            else              s_unass[n_unass++] = i;
        }
    }
    n_unass = __shfl_sync(0xffffffffu, n_unass, 0);
    __syncwarp();

    // Dijkstra augmentation for collided rows (rare), rows read from L2
    for (int ui = 0; ui < n_unass; ui++) {
        const int i = s_unass[ui];
#pragma unroll
        for (int k = 0; k < KMAX; k++) minv[k] = INFINITY;
        unsigned used = 0;
        int j0 = 0;
        if (lane == 0) s_p[0] = i;
        __syncwarp();

        while (true) {
            if (j0 > 0 && (((j0 - 1) & 31) == lane))
                used |= 1u << ((j0 - 1) >> 5);

            const int   i0   = s_p[j0];
            const float u_i0 = s_u[i0];
            const float* Crow = Cb + (size_t)(i0 - 1) * QQ;

            float best = INFINITY;
            int   bidx = QQ + 2;
#pragma unroll
            for (int k = 0; k < KMAX; k++) {
                int j = 1 + lane + 32 * k;
                if (j <= QQ && !((used >> k) & 1u)) {
                    float cur = __ldcg(&Crow[j - 1]) - u_i0 - v[k];
                    if (cur < minv[k]) { minv[k] = cur; s_way[j] = j0; }
                    if (minv[k] < best) { best = minv[k]; bidx = j; }
                }
            }
            float delta; int j1;
            warp_argmin(best, bidx, delta, j1);

#pragma unroll
            for (int k = 0; k < KMAX; k++) {
                int j = 1 + lane + 32 * k;
                if (j <= QQ) {
                    if ((used >> k) & 1u) {
                        v[k] -= delta;
                        s_u[s_p[j]] += delta;     // distinct p[j] across used cols
                    } else {
                        minv[k] -= delta;
                    }
                }
            }
            if (lane == 0) s_u[i] += delta;       // virtual column 0 (p[0] = i)
            __syncwarp();

            if (s_p[j1] == 0) { j0 = j1; break; }
            j0 = j1;
        }

        if (lane == 0) {
            int jj = j0;
            while (jj) {
                int jp = s_way[jj];
                s_p[jj] = s_p[jp];
                jj = jp;
            }
        }
        __syncwarp();
    }

    // sum selected float32 costs (optimal total is assignment-independent)
    double local = 0.0;
#pragma unroll
    for (int k = 0; k < KMAX; k++) {
        int j = 1 + lane + 32 * k;
        if (j <= QQ) {
            int pj = s_p[j];
            if (pj > 0) local += (double)__ldcg(&Cb[(size_t)(pj - 1) * QQ + (j - 1)]);
        }
    }
#pragma unroll
    for (int off = 16; off > 0; off >>= 1)
        local += __shfl_down_sync(0xffffffffu, local, off);
    if (lane == 0) {
        g_l1[b]  = local;
        g_cnt[b] = n;
        g_bce[b] = bce_row;
    }

    // ---- final combine: last LAP block, deterministic fixed-order sum ----
    __threadfence();
    unsigned old = 0;
    if (lane == 0) old = atomicAdd(&g_done, 1u);
    old = __shfl_sync(0xffffffffu, old, 0);
    if (old == BB - 1) {
        double l1 = 0.0, cnt = 0.0, bce = 0.0;
#pragma unroll
        for (int k = 0; k < BB / 32; k++) {
            int bb = lane + 32 * k;
            l1  += __ldcg(&g_l1[bb]);
            cnt += (double)__ldcg(&g_cnt[bb]);
            bce += __ldcg(&g_bce[bb]);
        }
#pragma unroll
        for (int off = 16; off > 0; off >>= 1) {
            l1  += __shfl_down_sync(0xffffffffu, l1, off);
            cnt += __shfl_down_sync(0xffffffffu, cnt, off);
            bce += __shfl_down_sync(0xffffffffu, bce, off);
        }
        if (lane == 0) {
            double loss1 = l1 / cnt;
            double loss5 = bce / (double)(BB * 32);
            out[0] = (float)(0.1 * loss1 + 1.0 * loss5);
            g_done = 0;                      // reset for next graph replay
        }
    }
}

// ---------------- launch ----------------
extern "C" void kernel_launch(void* const* d_in, const int* in_sizes, int n_in,
                              void* d_out, int out_size) {
    const float* pred_head = (const float*)d_in[0];
    const float* pred_rel  = (const float*)d_in[1];
    const float* pred_tail = (const float*)d_in[2];
    const float* IVT       = (const float*)d_in[3];
    const int*   iid       = (const int*)d_in[4];
    const int*   vid       = (const int*)d_in[5];
    const int*   tgt       = (const int*)d_in[6];
    // d_in[7..9] (instrument, verb, target) unused by the reference
    const int*   triplet   = (const int*)d_in[10];
    const int*   mask      = (const int*)d_in[11];
    float* out = (float*)d_out;

    fused_kernel<<<BB * 2, NTHR>>>(pred_head, pred_rel, pred_tail, IVT,
                                   iid, vid, tgt, triplet, mask, out);
}

// round 15
// speedup vs baseline: 1.7295x; 1.7295x over previous
#include <cuda_runtime.h>
#include <math.h>

#define BB 256
#define QQ 300
#define GG 16
#define KMAX 10   // ceil(QQ/32) columns per lane
#define NTHR 320  // one q per thread in phase 1; 10 warps
#define NW 10     // warps per block

#define SCR_W 25                           // 24 logits + pad, stride 25 (coprime to 32)
#define DYN_FLOATS (QQ * SCR_W + GG * QQ)  // 7500 + 4800 = 12300
#define DYN_BYTES (DYN_FLOATS * 4)         // 49200

// ---------------- device scratch (no allocations allowed) ----------------
__device__ double   g_l1[BB];             // per-batch selected-cost sum
__device__ double   g_bce[BB];            // per-batch weighted BCE sum
__device__ int      g_cnt[BB];            // per-batch nval
__device__ unsigned g_done = 0;           // done-counter (last block resets to 0)

__constant__ float c_tw[32] = {
    1.17236407f, 1.0166286f, 1.19620973f, 0.5544405f, 0.63531401f, 0.51258428f,
    1.08866652f, 1.15795989f, 1.07389395f, 0.98728399f, 1.12754142f, 1.05953744f,
    1.16945323f, 1.15512349f, 1.02097204f, 1.15795989f, 1.07147279f, 0.50627649f,
    1.07147279f, 0.61697221f, 1.16367678f, 1.0231585f, 1.18416106f, 1.04329092f,
    1.10645159f, 1.18416106f, 1.15795989f, 1.16367678f, 0.73949534f, 0.78760821f,
    1.08617476f, 1.00805777f
};

// order-preserving float <-> u32 key (finite + inf safe)
__device__ __forceinline__ unsigned f2key(float f) {
    unsigned u = __float_as_uint(f);
    return (u & 0x80000000u) ? ~u : (u | 0x80000000u);
}
__device__ __forceinline__ float key2f(unsigned k) {
    unsigned u = (k & 0x80000000u) ? (k & 0x7fffffffu) : ~k;
    return __uint_as_float(u);
}

// warp argmin (value, lowest index among minima)
__device__ __forceinline__ void warp_argmin(float val, int idx, float& mval, int& midx) {
    const unsigned mykey = f2key(val);
    const unsigned mkey  = __reduce_min_sync(0xffffffffu, mykey);
    const unsigned cand  = (mykey == mkey) ? (unsigned)idx : 0xffffffffu;
    midx = (int)__reduce_min_sync(0xffffffffu, cand);
    mval = key2f(mkey);
}

// ---- fused kernel ----
__global__ __launch_bounds__(NTHR, 2) void fused_kernel(
    const float* __restrict__ ph,
    const float* __restrict__ pr,
    const float* __restrict__ pt,
    const float* __restrict__ IVT,
    const int* __restrict__ iid,
    const int* __restrict__ vid,
    const int* __restrict__ tgt,
    const int* __restrict__ triplet,
    const int* __restrict__ mask,
    float* __restrict__ out)
{
    const int b   = blockIdx.x;
    const int tid = threadIdx.x;
    const int wrp = tid >> 5;
    const int lane = tid & 31;

    extern __shared__ float dyn[];
    float* s_scr = dyn;                  // [QQ][SCR_W]: 0..8 h, 9..21 r, 22..23 t
    float* Cm    = dyn + QQ * SCR_W;     // [GG][QQ] row-major

    __shared__ unsigned long long s_part[GG][NW];   // per-warp packed (key|j) row argmins
    __shared__ float s_u[GG + 1];
    __shared__ int   s_p[QQ + 1];
    __shared__ int   s_way[QQ + 1];
    __shared__ int   si[GG], sv[GG], st[GG];
    __shared__ int   s_unass[GG];

    // ---- phase 0: warp 0 computes this batch row's weighted BCE (overlapped) ----
    double bce_row = 0.0;
    if (tid < 32) {
        float x = IVT[b * 32 + tid];
        float t = (float)triplet[b * 32 + tid];
        float v = fmaxf(x, 0.f) - x * t + log1pf(__expf(-fabsf(x)));
        bce_row = (double)(c_tw[tid] * v);
#pragma unroll
        for (int off = 16; off > 0; off >>= 1)
            bce_row += __shfl_down_sync(0xffffffffu, bce_row, off);
    }

    if (tid < GG) {
        si[tid] = iid[b * GG + tid];
        sv[tid] = vid[b * GG + tid];
        st[tid] = tgt[b * GG + tid];
    }
    for (int j = tid; j <= QQ; j += NTHR) { s_p[j] = 0; s_way[j] = 0; }
    if (tid <= GG) s_u[tid] = 0.f;
    __syncthreads();

    // ---- phase 1: logits -> shared scratch + direct log-sum-exp; keep the 16
    //      costs of this thread's column in registers for the fused row-argmin ----
    float cv[GG];
#pragma unroll
    for (int g = 0; g < GG; g++) cv[g] = INFINITY;
    const int jglob = (tid < QQ) ? (tid + 1) : (QQ + 2);

    if (tid < QQ) {
        const int q = tid;
        float* scr = s_scr + q * SCR_W;
        const float* hp = ph + (size_t)(b * QQ + q) * 9;
        const float* rp = pr + (size_t)(b * QQ + q) * 13;
        const float* tp = pt + (size_t)(b * QQ + q) * 2;

        float sh = 0.f, sr = 0.f, stt = 0.f;
#pragma unroll
        for (int i = 0; i < 9; i++)  { float x = hp[i]; scr[i]      = x; sh  += __expf(x); }
#pragma unroll
        for (int i = 0; i < 13; i++) { float x = rp[i]; scr[9 + i]  = x; sr  += __expf(x); }
#pragma unroll
        for (int i = 0; i < 2; i++)  { float x = tp[i]; scr[22 + i] = x; stt += __expf(x); }

        const float lsum = __logf(sh) + __logf(sr) + __logf(stt);

        // gathers via LDS (strides conflict-free); write C and keep in registers
#pragma unroll
        for (int g = 0; g < GG; g++) {
            float c = lsum - (scr[si[g]] + scr[9 + sv[g]] + scr[22 + st[g]]);
            Cm[g * QQ + q] = c;
            cv[g] = c;
        }
    }

    // ---- phase 1b (fused): per-warp row argmins straight from registers ----
#pragma unroll
    for (int g = 0; g < GG; g++) {
        float mv; int mj;
        warp_argmin(cv[g], jglob, mv, mj);
        if (lane == 0)
            s_part[g][wrp] = ((unsigned long long)f2key(mv) << 32) | (unsigned)mj;
    }
    __syncthreads();

    // ---- phase 2: warp 0 solves the LAP ----
    if (tid >= 32) return;

    // merge per-warp partial argmins (lowest key, then lowest j — exact semantics)
    float rmin_l = 0.f; int jm_l = 0;
    if (lane < GG) {
        unsigned long long m = s_part[lane][0];
#pragma unroll
        for (int w = 1; w < NW; w++) m = min(m, s_part[lane][w]);
        rmin_l = key2f((unsigned)(m >> 32));
        jm_l   = (int)(m & 0xffffffffu);
    }

    unsigned mb = __ballot_sync(0xffffffffu, lane < GG && mask[b * GG + lane] != 0);
    const int n = __popc(mb);

    float v[KMAX], minv[KMAX];
#pragma unroll
    for (int k = 0; k < KMAX; k++) v[k] = 0.f;

    // -- phase 2a: greedy init from merged row minima (lane 0, trivial) --
    __syncwarp();
    int n_unass = 0;
    for (int i = 1; i <= n; i++) {
        float ru = __shfl_sync(0xffffffffu, rmin_l, i - 1);
        int   jm = __shfl_sync(0xffffffffu, jm_l,   i - 1);
        if (lane == 0) {
            s_u[i] = ru;
            if (s_p[jm] == 0) s_p[jm] = i;
            else              s_unass[n_unass++] = i;
        }
    }
    n_unass = __shfl_sync(0xffffffffu, n_unass, 0);
    __syncwarp();

    // -- phase 2b: Dijkstra augmentation for unassigned rows only --
    for (int ui = 0; ui < n_unass; ui++) {
        const int i = s_unass[ui];
#pragma unroll
        for (int k = 0; k < KMAX; k++) minv[k] = INFINITY;
        unsigned used = 0;
        int j0 = 0;
        if (lane == 0) s_p[0] = i;
        __syncwarp();

        while (true) {
            if (j0 > 0 && (((j0 - 1) & 31) == lane))
                used |= 1u << ((j0 - 1) >> 5);

            const int   i0   = s_p[j0];
            const float u_i0 = s_u[i0];
            const float* Crow = Cm + (i0 - 1) * QQ;

            float best = INFINITY;
            int   bidx = QQ + 2;
#pragma unroll
            for (int k = 0; k < KMAX; k++) {
                int j = 1 + lane + 32 * k;
                if (j <= QQ && !((used >> k) & 1u)) {
                    float cur = Crow[j - 1] - u_i0 - v[k];
                    if (cur < minv[k]) { minv[k] = cur; s_way[j] = j0; }
                    if (minv[k] < best) { best = minv[k]; bidx = j; }
                }
            }
            float delta; int j1;
            warp_argmin(best, bidx, delta, j1);

#pragma unroll
            for (int k = 0; k < KMAX; k++) {
                int j = 1 + lane + 32 * k;
                if (j <= QQ) {
                    if ((used >> k) & 1u) {
                        v[k] -= delta;
                        s_u[s_p[j]] += delta;     // distinct p[j] across used cols
                    } else {
                        minv[k] -= delta;
                    }
                }
            }
            if (lane == 0) s_u[i] += delta;       // virtual column 0 (p[0] = i)
            __syncwarp();

            if (s_p[j1] == 0) { j0 = j1; break; }
            j0 = j1;
        }

        // augment alternating path
        if (lane == 0) {
            int jj = j0;
            while (jj) {
                int jp = s_way[jj];
                s_p[jj] = s_p[jp];
                jj = jp;
            }
        }
        __syncwarp();
    }

    // sum selected float32 costs (optimal total is assignment-independent)
    double local = 0.0;
#pragma unroll
    for (int k = 0; k < KMAX; k++) {
        int j = 1 + lane + 32 * k;
        if (j <= QQ) {
            int pj = s_p[j];
            if (pj > 0) local += (double)Cm[(pj - 1) * QQ + (j - 1)];
        }
    }
#pragma unroll
    for (int off = 16; off > 0; off >>= 1)
        local += __shfl_down_sync(0xffffffffu, local, off);
    if (lane == 0) {
        g_l1[b]  = local;
        g_cnt[b] = n;
        g_bce[b] = bce_row;
    }

    // ---- phase 3: last block performs the final combine (deterministic order) ----
    __threadfence();
    unsigned old = 0;
    if (lane == 0) old = atomicAdd(&g_done, 1u);
    old = __shfl_sync(0xffffffffu, old, 0);
    if (old == BB - 1) {
        double l1 = 0.0, cnt = 0.0, bce = 0.0;
#pragma unroll
        for (int k = 0; k < BB / 32; k++) {
            int bb = lane + 32 * k;
            l1  += __ldcg(&g_l1[bb]);
            cnt += (double)__ldcg(&g_cnt[bb]);
            bce += __ldcg(&g_bce[bb]);
        }
#pragma unroll
        for (int off = 16; off > 0; off >>= 1) {
            l1  += __shfl_down_sync(0xffffffffu, l1, off);
            cnt += __shfl_down_sync(0xffffffffu, cnt, off);
            bce += __shfl_down_sync(0xffffffffu, bce, off);
        }
        if (lane == 0) {
            double loss1 = l1 / cnt;
            double loss5 = bce / (double)(BB * 32);
            out[0] = (float)(0.1 * loss1 + 1.0 * loss5);
            g_done = 0;                      // reset for next graph replay
        }
    }
}

// ---------------- launch ----------------
extern "C" void kernel_launch(void* const* d_in, const int* in_sizes, int n_in,
                              void* d_out, int out_size) {
    const float* pred_head = (const float*)d_in[0];
    const float* pred_rel  = (const float*)d_in[1];
    const float* pred_tail = (const float*)d_in[2];
    const float* IVT       = (const float*)d_in[3];
    const int*   iid       = (const int*)d_in[4];
    const int*   vid       = (const int*)d_in[5];
    const int*   tgt       = (const int*)d_in[6];
    // d_in[7..9] (instrument, verb, target) unused by the reference
    const int*   triplet   = (const int*)d_in[10];
    const int*   mask      = (const int*)d_in[11];
    float* out = (float*)d_out;

    static bool attr_set = false;
    if (!attr_set) {
        cudaFuncSetAttribute(fused_kernel,
                             cudaFuncAttributeMaxDynamicSharedMemorySize, DYN_BYTES);
        attr_set = true;
    }

    fused_kernel<<<BB, NTHR, DYN_BYTES>>>(pred_head, pred_rel, pred_tail, IVT,
                                          iid, vid, tgt, triplet, mask, out);
}